// round 15
// baseline (speedup 1.0000x reference)
#include <cuda_runtime.h>
#include <cuda_fp16.h>
#include <cstdint>

#define Nn   100000
#define Ee   800000
#define Dd   384
#define OUTC 2

// ---------------- device scratch (no allocations allowed) ----------------
__device__ __half g_xh[(size_t)Nn * Dd];    // 76.8 MB  fp16 copy of x
__device__ __half g_meanh[(size_t)Nn * Dd]; // 76.8 MB  aggregated mean (fp16)
__device__ __half g_hh[(size_t)Nn * Dd];    // 76.8 MB  layer-1 output (fp16)
__device__ __half g_Wh[4][Dd * Dd];         // fp16 weights, TRANSPOSED [N][K]
__device__ float  g_fpart[(size_t)Nn * 12]; // head partials [row][slot0..5][2]
__device__ int    g_deg[Nn];                // zero at load; re-zeroed by k_scan23
__device__ int    g_ptr[Nn + 1];
__device__ int    g_cursor[Nn];
__device__ int    g_col[Ee];
__device__ float  g_wt[Ee];
__device__ int    g_part[128];

// ---------------- helpers ----------------
__device__ __forceinline__ void cp16(void* smem, const void* g, bool pred) {
    uint32_t s = (uint32_t)__cvta_generic_to_shared(smem);
    int bytes = pred ? 16 : 0;
    asm volatile("cp.async.cg.shared.global [%0], [%1], 16, %2;\n"
                 :: "r"(s), "l"(g), "r"(bytes));
}
#define CP_COMMIT() asm volatile("cp.async.commit_group;\n" ::: "memory")
#define CP_WAIT(n)  asm volatile("cp.async.wait_group %0;\n" :: "n"(n) : "memory")

__device__ __forceinline__ void mma_f16(float* d, const uint32_t* a, const uint32_t* b) {
    asm volatile(
        "mma.sync.aligned.m16n8k16.row.col.f32.f16.f16.f32 "
        "{%0,%1,%2,%3}, {%4,%5,%6,%7}, {%8,%9}, {%0,%1,%2,%3};\n"
        : "+f"(d[0]), "+f"(d[1]), "+f"(d[2]), "+f"(d[3])
        : "r"(a[0]), "r"(a[1]), "r"(a[2]), "r"(a[3]), "r"(b[0]), "r"(b[1]));
}

// jnp.int64 may be canonicalized to int32 by JAX. If data really is int64
// (LE, values < 2^32), every odd int32 word is 0. 16 random indices in
// [0,100000) all having zero high words is impossible.
__device__ __forceinline__ bool probe64(const int* __restrict__ ei) {
    bool is64 = true;
#pragma unroll
    for (int j = 1; j < 32; j += 2) is64 &= (ei[j] == 0);
    return is64;
}
__device__ __forceinline__ int edge_at(const void* ei, int pos, bool is64) {
    return is64 ? (int)((const long long*)ei)[pos] : ((const int*)ei)[pos];
}

__device__ __forceinline__ void acc8(float* acc, uint4 u, float w) {
    float2 f;
    f = __half22float2(*(__half2*)&u.x); acc[0] += w * f.x; acc[1] += w * f.y;
    f = __half22float2(*(__half2*)&u.y); acc[2] += w * f.x; acc[3] += w * f.y;
    f = __half22float2(*(__half2*)&u.z); acc[4] += w * f.x; acc[5] += w * f.y;
    f = __half22float2(*(__half2*)&u.w); acc[6] += w * f.x; acc[7] += w * f.y;
}
__device__ __forceinline__ uint4 pack8(const float* a, float inv) {
    uint4 o; __half2 h;
    h = __floats2half2_rn(a[0] * inv, a[1] * inv); o.x = *(uint32_t*)&h;
    h = __floats2half2_rn(a[2] * inv, a[3] * inv); o.y = *(uint32_t*)&h;
    h = __floats2half2_rn(a[4] * inv, a[5] * inv); o.z = *(uint32_t*)&h;
    h = __floats2half2_rn(a[6] * inv, a[7] * inv); o.w = *(uint32_t*)&h;
    return o;
}

// ---------------- init: x->fp16 (x4 vectorized), weights, degree count ------
// 9375 blocks x 1024 threads = Nn*Dd/4 threads.
__global__ void k_init(const int* __restrict__ ei,
                       const float* __restrict__ x,
                       const float* __restrict__ w0, const float* __restrict__ w1,
                       const float* __restrict__ w2, const float* __restrict__ w3) {
    size_t i = (size_t)blockIdx.x * blockDim.x + threadIdx.x;
    float4 v = ((const float4*)x)[i];
    __half2 h0 = __floats2half2_rn(v.x, v.y);
    __half2 h1 = __floats2half2_rn(v.z, v.w);
    uint2 o; o.x = *(uint32_t*)&h0; o.y = *(uint32_t*)&h1;
    ((uint2*)g_xh)[i] = o;
    if (i < Dd * Dd) {
        int k = (int)i / Dd, n = (int)i % Dd;
        int t = n * Dd + k;                 // transpose [K][N] -> [N][K]
        g_Wh[0][t] = __float2half_rn(w0[i]);
        g_Wh[1][t] = __float2half_rn(w1[i]);
        g_Wh[2][t] = __float2half_rn(w2[i]);
        g_Wh[3][t] = __float2half_rn(w3[i]);
    }
    if (i < Ee) {
        bool is64 = probe64(ei);
        atomicAdd(&g_deg[edge_at(ei, Ee + (int)i, is64)], 1);
    }
}

// ---------------- CSR scan (two kernels, full-grid finalize) ----------------
__global__ void k_scan1() {
    __shared__ int s[1024];
    int tid = threadIdx.x;
    int i = blockIdx.x * 1024 + tid;
    int v = (i < Nn) ? g_deg[i] : 0;
    s[tid] = v;
    __syncthreads();
    for (int off = 1; off < 1024; off <<= 1) {
        int t = (tid >= off) ? s[tid - off] : 0;
        __syncthreads();
        s[tid] += t;
        __syncthreads();
    }
    if (i < Nn) g_ptr[i] = s[tid];
    if (tid == 1023) g_part[blockIdx.x] = s[1023];
}
__global__ void k_scan23() {
    int i = blockIdx.x * blockDim.x + threadIdx.x;
    if (i < Nn) {
        int nb = i >> 10;
        int run = 0;
        for (int b = 0; b < nb; b++) run += g_part[b];
        int excl = g_ptr[i] - g_deg[i] + run;
        g_ptr[i] = excl;
        g_cursor[i] = excl;
        g_deg[i] = 0;                 // invariant: deg zeroed after consumption
    }
    if (i == 0) g_ptr[Nn] = Ee;
}
__global__ void k_fill(const void* __restrict__ ei, const float* __restrict__ ew) {
    int e = blockIdx.x * blockDim.x + threadIdx.x;
    if (e < Ee) {
        bool is64 = probe64((const int*)ei);
        int s = edge_at(ei, e, is64);
        int d = edge_at(ei, Ee + e, is64);
        int pos = atomicAdd(&g_cursor[d], 1);
        g_col[pos] = s;
        g_wt[pos] = ew[e];
    }
}

// ---------------- mean aggregation: warp per dst node, uint4 x4-unroll ------
// (measured 107.6us/pass)
__global__ void k_agg(int layer) {
    int gw = (blockIdx.x * blockDim.x + threadIdx.x) >> 5;
    int lane = threadIdx.x & 31;
    if (gw >= Nn) return;
    const uint4* X = (const uint4*)(layer == 1 ? g_xh : g_hh);  // 48 per row
    int s = g_ptr[gw], eEnd = g_ptr[gw + 1];
    const bool lo = lane < 16;
    float accA[8] = {0,0,0,0,0,0,0,0};
    float accB[8] = {0,0,0,0,0,0,0,0};
    int e = s;
    for (; e + 3 < eEnd; e += 4) {
        int s0 = g_col[e],     s1 = g_col[e + 1];
        int s2 = g_col[e + 2], s3 = g_col[e + 3];
        float w0 = g_wt[e],     w1 = g_wt[e + 1];
        float w2 = g_wt[e + 2], w3 = g_wt[e + 3];
        const uint4* r0 = X + (size_t)s0 * 48;
        const uint4* r1 = X + (size_t)s1 * 48;
        const uint4* r2 = X + (size_t)s2 * 48;
        const uint4* r3 = X + (size_t)s3 * 48;
        uint4 a0 = __ldg(r0 + lane), a1 = __ldg(r1 + lane);
        uint4 a2 = __ldg(r2 + lane), a3 = __ldg(r3 + lane);
        uint4 b0, b1, b2, b3;
        if (lo) {
            b0 = __ldg(r0 + 32 + lane); b1 = __ldg(r1 + 32 + lane);
            b2 = __ldg(r2 + 32 + lane); b3 = __ldg(r3 + 32 + lane);
        }
        acc8(accA, a0, w0); acc8(accA, a1, w1);
        acc8(accA, a2, w2); acc8(accA, a3, w3);
        if (lo) {
            acc8(accB, b0, w0); acc8(accB, b1, w1);
            acc8(accB, b2, w2); acc8(accB, b3, w3);
        }
    }
    for (; e < eEnd; e++) {
        int s0 = g_col[e];
        float w0 = g_wt[e];
        const uint4* r0 = X + (size_t)s0 * 48;
        uint4 a0 = __ldg(r0 + lane);
        acc8(accA, a0, w0);
        if (lo) { uint4 b0 = __ldg(r0 + 32 + lane); acc8(accB, b0, w0); }
    }
    float inv = 1.f / fmaxf((float)(eEnd - s), 1.f);
    uint4* mr = (uint4*)(g_meanh + (size_t)gw * Dd);
    mr[lane] = pack8(accA, inv);
    if (lo) mr[32 + lane] = pack8(accB, inv);
}

// ---------------- fused GraphConv GEMM (fp16 m16n8k16), 3-stage pipe --------
// Od = relu(mean @ Wrel + A2 @ Wroot + brel)
// 128x128 CTA tile, BK=32, 4 warps of 64x64, THREE cp.async buffers with ONE
// __syncthreads per K-iteration (stage(it+2) overwrites the buffer of
// compute(it-1); the barrier at the top of it orders all warps past
// compute(it-1), so the trailing barrier of the 2-stage loop is redundant).
// 61.4KB dynamic smem x 2 CTAs/SM = 123KB < 227KB: occupancy unchanged vs the
// measured 774us config. Layer 2 also emits head partials (y @ W_lin) into
// g_fpart (deterministic slots, no atomics); k_sig reduces them.
#define BM 128
#define BN 128
#define BK 32
#define PITCH 40                 // halves per smem row; conflict-free word perm
#define TILEB (128 * PITCH * 2)  // 10240 bytes per tile
#define BUFB  (2 * TILEB)        // A + B per buffer = 20480
#define SMEMB (3 * BUFB)         // 61440 bytes

__global__ __launch_bounds__(128, 2) void k_layer_mma(
    const float* __restrict__ brel,
    const float* __restrict__ Wl,
    float* __restrict__ yout, int layer)
{
    extern __shared__ char sm[];

    const __half* A2    = (layer == 1) ? g_xh : g_hh;
    const __half* Wrel  = g_Wh[(layer == 1) ? 0 : 2];   // [N][K] fp16
    const __half* Wroot = g_Wh[(layer == 1) ? 1 : 3];

    const int t = threadIdx.x;
    const int warp = t >> 5, lane = t & 31;
    const int warpM = warp >> 1, warpN = warp & 1;       // 2x2 of 64x64 tiles
    const int g = lane >> 2, t4 = lane & 3;
    const int rowBase = blockIdx.y * BM;
    const int colBase = blockIdx.x * BN;

    float acc[4][8][4];
#pragma unroll
    for (int mm = 0; mm < 4; mm++)
#pragma unroll
        for (int nn = 0; nn < 8; nn++)
#pragma unroll
            for (int q = 0; q < 4; q++) acc[mm][nn][q] = 0.f;

    // 24 K-iterations: it<12 -> (g_meanh, Wrel); it>=12 -> (A2, Wroot)
    auto stage = [&](int it, int buf) {
        const __half* A = (it < 12) ? g_meanh : A2;
        const __half* W = (it < 12) ? Wrel : Wroot;
        int k0 = (it % 12) * BK;
        char* As = sm + buf * BUFB;
        char* Bs = As + TILEB;
#pragma unroll
        for (int i = 0; i < 4; i++) {
            int c = t + i * 128;          // 512 16B chunks each for A and B
            int r = c >> 2;               // tile row 0..127
            int o = (c & 3) * 8;          // half offset within row
            int boff = r * (PITCH * 2) + (c & 3) * 16;
            int grow = rowBase + r;
            cp16(As + boff, A + (size_t)grow * Dd + k0 + o, grow < Nn);
            cp16(Bs + boff, W + (size_t)(colBase + r) * Dd + k0 + o, true);
        }
    };

    auto compute = [&](int buf) {
        const uint32_t* As32 = (const uint32_t*)(sm + buf * BUFB);
        const uint32_t* Bs32 = (const uint32_t*)(sm + buf * BUFB + TILEB);
#pragma unroll
        for (int ks = 0; ks < 2; ks++) {           // two k16 steps per BK=32
            const int kw = ks * 8 + t4;            // b32 word offset in row
            uint32_t a[4][4], b[8][2];
#pragma unroll
            for (int mm = 0; mm < 4; mm++) {
                int r = warpM * 64 + mm * 16 + g;
                a[mm][0] = As32[r * (PITCH / 2) + kw];
                a[mm][1] = As32[(r + 8) * (PITCH / 2) + kw];
                a[mm][2] = As32[r * (PITCH / 2) + kw + 4];
                a[mm][3] = As32[(r + 8) * (PITCH / 2) + kw + 4];
            }
#pragma unroll
            for (int nn = 0; nn < 8; nn++) {
                int n = warpN * 64 + nn * 8 + g;
                b[nn][0] = Bs32[n * (PITCH / 2) + kw];
                b[nn][1] = Bs32[n * (PITCH / 2) + kw + 4];
            }
#pragma unroll
            for (int mm = 0; mm < 4; mm++)
#pragma unroll
                for (int nn = 0; nn < 8; nn++)
                    mma_f16(acc[mm][nn], a[mm], b[nn]);
        }
    };

    stage(0, 0); CP_COMMIT();
    stage(1, 1); CP_COMMIT();
#pragma unroll 1
    for (int it = 0; it < 24; it++) {
        if (it < 23) { CP_WAIT(1); } else { CP_WAIT(0); }
        __syncthreads();                                 // ONE barrier per iter
        if (it + 2 < 24) { stage(it + 2, (it + 2) % 3); CP_COMMIT(); }
        compute(it % 3);
    }

    // epilogue: bias + relu (+ head partials on layer 2)
    const int slot = blockIdx.x * 2 + warpN;   // 0..5 head-partial slot
#pragma unroll
    for (int mm = 0; mm < 4; mm++) {
        float p00 = 0.f, p01 = 0.f, p10 = 0.f, p11 = 0.f;
#pragma unroll
        for (int nn = 0; nn < 8; nn++) {
            int c = colBase + warpN * 64 + nn * 8 + t4 * 2;
            float b0 = brel[c], b1 = brel[c + 1];
            int r0 = rowBase + warpM * 64 + mm * 16 + g;
            int r1 = r0 + 8;
            float v00 = fmaxf(acc[mm][nn][0] + b0, 0.f);
            float v01 = fmaxf(acc[mm][nn][1] + b1, 0.f);
            float v10 = fmaxf(acc[mm][nn][2] + b0, 0.f);
            float v11 = fmaxf(acc[mm][nn][3] + b1, 0.f);
            if (layer == 1) {
                if (r0 < Nn) {
                    __half2 h = __floats2half2_rn(v00, v01);
                    *(__half2*)(g_hh + (size_t)r0 * Dd + c) = h;
                }
                if (r1 < Nn) {
                    __half2 h = __floats2half2_rn(v10, v11);
                    *(__half2*)(g_hh + (size_t)r1 * Dd + c) = h;
                }
            } else {
                if (r0 < Nn) *(float2*)(yout + (size_t)r0 * Dd + c) = make_float2(v00, v01);
                if (r1 < Nn) *(float2*)(yout + (size_t)r1 * Dd + c) = make_float2(v10, v11);
                float wl0a = __ldg(Wl + c * 2),     wl1a = __ldg(Wl + c * 2 + 1);
                float wl0b = __ldg(Wl + c * 2 + 2), wl1b = __ldg(Wl + c * 2 + 3);
                p00 += v00 * wl0a + v01 * wl0b;
                p01 += v00 * wl1a + v01 * wl1b;
                p10 += v10 * wl0a + v11 * wl0b;
                p11 += v10 * wl1a + v11 * wl1b;
            }
        }
        if (layer == 2) {
            // reduce across the t4 quad (lanes differ in bits 0..1)
#pragma unroll
            for (int m = 1; m <= 2; m <<= 1) {
                p00 += __shfl_xor_sync(0xffffffffu, p00, m);
                p01 += __shfl_xor_sync(0xffffffffu, p01, m);
                p10 += __shfl_xor_sync(0xffffffffu, p10, m);
                p11 += __shfl_xor_sync(0xffffffffu, p11, m);
            }
            if (t4 == 0) {
                int r0 = rowBase + warpM * 64 + mm * 16 + g;
                int r1 = r0 + 8;
                if (r0 < Nn) {
                    g_fpart[(size_t)r0 * 12 + slot * 2 + 0] = p00;
                    g_fpart[(size_t)r0 * 12 + slot * 2 + 1] = p01;
                }
                if (r1 < Nn) {
                    g_fpart[(size_t)r1 * 12 + slot * 2 + 0] = p10;
                    g_fpart[(size_t)r1 * 12 + slot * 2 + 1] = p11;
                }
            }
        }
    }
}

// ---------------- head: sum 6 slots + bias + sigmoid ----------------
__global__ void k_sig(const float* __restrict__ bl, float* __restrict__ out) {
    int r = blockIdx.x * blockDim.x + threadIdx.x;
    if (r >= Nn) return;
    const float* p = g_fpart + (size_t)r * 12;
    float s0 = bl[0], s1 = bl[1];
#pragma unroll
    for (int s = 0; s < 6; s++) { s0 += p[s * 2]; s1 += p[s * 2 + 1]; }
    out[r * 2 + 0] = 1.f / (1.f + expf(-s0));
    out[r * 2 + 1] = 1.f / (1.f + expf(-s1));
}

// ---------------- launch ----------------
extern "C" void kernel_launch(void* const* d_in, const int* in_sizes, int n_in,
                              void* d_out, int out_size)
{
    const float* x   = (const float*)d_in[0];
    const void*  ei  = d_in[1];
    const float* ew  = (const float*)d_in[2];
    const float* br1 = (const float*)d_in[4];
    const float* br2 = (const float*)d_in[7];
    const float* Wl  = (const float*)d_in[9];
    const float* bl  = (const float*)d_in[10];

    float* out = (float*)d_out;                 // [N, 2]
    float* y   = out + (size_t)Nn * OUTC;       // [N, 384]

    (void)cudaFuncSetAttribute(k_layer_mma,
                               cudaFuncAttributeMaxDynamicSharedMemorySize,
                               SMEMB);

    dim3 gg(Dd / BN, (Nn + BM - 1) / BM);       // (3, 782)

    k_init<<<9375, 1024>>>((const int*)ei, x,
                           (const float*)d_in[3], (const float*)d_in[5],
                           (const float*)d_in[6], (const float*)d_in[8]);    // 1
    k_scan1<<<(Nn + 1023) / 1024, 1024>>>();                                  // 2
    k_scan23<<<(Nn + 255) / 256, 256>>>();                                    // 3
    k_fill<<<(Ee + 255) / 256, 256>>>(ei, ew);                                // 4
    k_agg<<<(Nn * 32 + 255) / 256, 256>>>(1);                                 // 5
    k_layer_mma<<<gg, 128, SMEMB>>>(br1, Wl, nullptr, 1);                     // 6
    k_agg<<<(Nn * 32 + 255) / 256, 256>>>(2);                                 // 7
    k_layer_mma<<<gg, 128, SMEMB>>>(br2, Wl, y, 2);                           // 8
    k_sig<<<(Nn + 255) / 256, 256>>>(bl, out);                                // 9
}

// round 16
// speedup vs baseline: 1.0065x; 1.0065x over previous
#include <cuda_runtime.h>
#include <cuda_fp16.h>
#include <cstdint>

#define Nn   100000
#define Ee   800000
#define Dd   384
#define OUTC 2

// ---------------- device scratch (no allocations allowed) ----------------
__device__ __half g_xh[(size_t)Nn * Dd];    // 76.8 MB  fp16 copy of x
__device__ __half g_meanh[(size_t)Nn * Dd]; // 76.8 MB  aggregated mean (fp16)
__device__ __half g_hh[(size_t)Nn * Dd];    // 76.8 MB  layer-1 output (fp16)
__device__ __half g_Wh[4][Dd * Dd];         // fp16 weights, TRANSPOSED [N][K]
__device__ float  g_fpart[(size_t)Nn * 12]; // head partials [row][slot0..5][2]
__device__ int    g_deg[Nn];                // zero at load; re-zeroed by k_scan23
__device__ int    g_ptr[Nn + 1];
__device__ int    g_cursor[Nn];
__device__ int    g_col[Ee];
__device__ float  g_wt[Ee];
__device__ int    g_part[128];

// ---------------- helpers ----------------
__device__ __forceinline__ void cp16(void* smem, const void* g, bool pred) {
    uint32_t s = (uint32_t)__cvta_generic_to_shared(smem);
    int bytes = pred ? 16 : 0;
    asm volatile("cp.async.cg.shared.global [%0], [%1], 16, %2;\n"
                 :: "r"(s), "l"(g), "r"(bytes));
}
#define CP_COMMIT() asm volatile("cp.async.commit_group;\n" ::: "memory")
#define CP_WAIT(n)  asm volatile("cp.async.wait_group %0;\n" :: "n"(n) : "memory")

__device__ __forceinline__ void mma_f16(float* d, const uint32_t* a, const uint32_t* b) {
    asm volatile(
        "mma.sync.aligned.m16n8k16.row.col.f32.f16.f16.f32 "
        "{%0,%1,%2,%3}, {%4,%5,%6,%7}, {%8,%9}, {%0,%1,%2,%3};\n"
        : "+f"(d[0]), "+f"(d[1]), "+f"(d[2]), "+f"(d[3])
        : "r"(a[0]), "r"(a[1]), "r"(a[2]), "r"(a[3]), "r"(b[0]), "r"(b[1]));
}

// jnp.int64 may be canonicalized to int32 by JAX. If data really is int64
// (LE, values < 2^32), every odd int32 word is 0. 16 random indices in
// [0,100000) all having zero high words is impossible.
__device__ __forceinline__ bool probe64(const int* __restrict__ ei) {
    bool is64 = true;
#pragma unroll
    for (int j = 1; j < 32; j += 2) is64 &= (ei[j] == 0);
    return is64;
}
__device__ __forceinline__ int edge_at(const void* ei, int pos, bool is64) {
    return is64 ? (int)((const long long*)ei)[pos] : ((const int*)ei)[pos];
}

__device__ __forceinline__ void acc8(float* acc, uint4 u, float w) {
    float2 f;
    f = __half22float2(*(__half2*)&u.x); acc[0] += w * f.x; acc[1] += w * f.y;
    f = __half22float2(*(__half2*)&u.y); acc[2] += w * f.x; acc[3] += w * f.y;
    f = __half22float2(*(__half2*)&u.z); acc[4] += w * f.x; acc[5] += w * f.y;
    f = __half22float2(*(__half2*)&u.w); acc[6] += w * f.x; acc[7] += w * f.y;
}
__device__ __forceinline__ uint4 pack8(const float* a, float inv) {
    uint4 o; __half2 h;
    h = __floats2half2_rn(a[0] * inv, a[1] * inv); o.x = *(uint32_t*)&h;
    h = __floats2half2_rn(a[2] * inv, a[3] * inv); o.y = *(uint32_t*)&h;
    h = __floats2half2_rn(a[4] * inv, a[5] * inv); o.z = *(uint32_t*)&h;
    h = __floats2half2_rn(a[6] * inv, a[7] * inv); o.w = *(uint32_t*)&h;
    return o;
}

// ---------------- init: x->fp16 (x4 vectorized), weights, degree count ------
// 9375 blocks x 1024 threads = Nn*Dd/4 threads.
__global__ void k_init(const int* __restrict__ ei,
                       const float* __restrict__ x,
                       const float* __restrict__ w0, const float* __restrict__ w1,
                       const float* __restrict__ w2, const float* __restrict__ w3) {
    size_t i = (size_t)blockIdx.x * blockDim.x + threadIdx.x;
    float4 v = ((const float4*)x)[i];
    __half2 h0 = __floats2half2_rn(v.x, v.y);
    __half2 h1 = __floats2half2_rn(v.z, v.w);
    uint2 o; o.x = *(uint32_t*)&h0; o.y = *(uint32_t*)&h1;
    ((uint2*)g_xh)[i] = o;
    if (i < Dd * Dd) {
        int k = (int)i / Dd, n = (int)i % Dd;
        int t = n * Dd + k;                 // transpose [K][N] -> [N][K]
        g_Wh[0][t] = __float2half_rn(w0[i]);
        g_Wh[1][t] = __float2half_rn(w1[i]);
        g_Wh[2][t] = __float2half_rn(w2[i]);
        g_Wh[3][t] = __float2half_rn(w3[i]);
    }
    if (i < Ee) {
        bool is64 = probe64(ei);
        atomicAdd(&g_deg[edge_at(ei, Ee + (int)i, is64)], 1);
    }
}

// ---------------- CSR scan (two kernels, full-grid finalize) ----------------
__global__ void k_scan1() {
    __shared__ int s[1024];
    int tid = threadIdx.x;
    int i = blockIdx.x * 1024 + tid;
    int v = (i < Nn) ? g_deg[i] : 0;
    s[tid] = v;
    __syncthreads();
    for (int off = 1; off < 1024; off <<= 1) {
        int t = (tid >= off) ? s[tid - off] : 0;
        __syncthreads();
        s[tid] += t;
        __syncthreads();
    }
    if (i < Nn) g_ptr[i] = s[tid];
    if (tid == 1023) g_part[blockIdx.x] = s[1023];
}
__global__ void k_scan23() {
    int i = blockIdx.x * blockDim.x + threadIdx.x;
    if (i < Nn) {
        int nb = i >> 10;
        int run = 0;
        for (int b = 0; b < nb; b++) run += g_part[b];
        int excl = g_ptr[i] - g_deg[i] + run;
        g_ptr[i] = excl;
        g_cursor[i] = excl;
        g_deg[i] = 0;                 // invariant: deg zeroed after consumption
    }
    if (i == 0) g_ptr[Nn] = Ee;
}
__global__ void k_fill(const void* __restrict__ ei, const float* __restrict__ ew) {
    int e = blockIdx.x * blockDim.x + threadIdx.x;
    if (e < Ee) {
        bool is64 = probe64((const int*)ei);
        int s = edge_at(ei, e, is64);
        int d = edge_at(ei, Ee + e, is64);
        int pos = atomicAdd(&g_cursor[d], 1);
        g_col[pos] = s;
        g_wt[pos] = ew[e];
    }
}

// ---------------- mean aggregation: warp per dst node, uint4 x4-unroll ------
// (measured 107.6us/pass)
__global__ void k_agg(int layer) {
    int gw = (blockIdx.x * blockDim.x + threadIdx.x) >> 5;
    int lane = threadIdx.x & 31;
    if (gw >= Nn) return;
    const uint4* X = (const uint4*)(layer == 1 ? g_xh : g_hh);  // 48 per row
    int s = g_ptr[gw], eEnd = g_ptr[gw + 1];
    const bool lo = lane < 16;
    float accA[8] = {0,0,0,0,0,0,0,0};
    float accB[8] = {0,0,0,0,0,0,0,0};
    int e = s;
    for (; e + 3 < eEnd; e += 4) {
        int s0 = g_col[e],     s1 = g_col[e + 1];
        int s2 = g_col[e + 2], s3 = g_col[e + 3];
        float w0 = g_wt[e],     w1 = g_wt[e + 1];
        float w2 = g_wt[e + 2], w3 = g_wt[e + 3];
        const uint4* r0 = X + (size_t)s0 * 48;
        const uint4* r1 = X + (size_t)s1 * 48;
        const uint4* r2 = X + (size_t)s2 * 48;
        const uint4* r3 = X + (size_t)s3 * 48;
        uint4 a0 = __ldg(r0 + lane), a1 = __ldg(r1 + lane);
        uint4 a2 = __ldg(r2 + lane), a3 = __ldg(r3 + lane);
        uint4 b0, b1, b2, b3;
        if (lo) {
            b0 = __ldg(r0 + 32 + lane); b1 = __ldg(r1 + 32 + lane);
            b2 = __ldg(r2 + 32 + lane); b3 = __ldg(r3 + 32 + lane);
        }
        acc8(accA, a0, w0); acc8(accA, a1, w1);
        acc8(accA, a2, w2); acc8(accA, a3, w3);
        if (lo) {
            acc8(accB, b0, w0); acc8(accB, b1, w1);
            acc8(accB, b2, w2); acc8(accB, b3, w3);
        }
    }
    for (; e < eEnd; e++) {
        int s0 = g_col[e];
        float w0 = g_wt[e];
        const uint4* r0 = X + (size_t)s0 * 48;
        uint4 a0 = __ldg(r0 + lane);
        acc8(accA, a0, w0);
        if (lo) { uint4 b0 = __ldg(r0 + 32 + lane); acc8(accB, b0, w0); }
    }
    float inv = 1.f / fmaxf((float)(eEnd - s), 1.f);
    uint4* mr = (uint4*)(g_meanh + (size_t)gw * Dd);
    mr[lane] = pack8(accA, inv);
    if (lo) mr[32 + lane] = pack8(accB, inv);
}

// ---------------- fused GraphConv GEMM (fp16 m16n8k16), 3-stage pipe --------
// Od = relu(mean @ Wrel + A2 @ Wroot + brel)
// 128x128 CTA tile, BK=32, 4 warps of 64x64, THREE cp.async buffers with ONE
// __syncthreads per K-iteration (stage(it+2) overwrites the buffer of
// compute(it-1); the barrier at the top of it orders all warps past
// compute(it-1), so the trailing barrier of the 2-stage loop is redundant).
// 61.4KB dynamic smem x 2 CTAs/SM = 123KB < 227KB: occupancy unchanged vs the
// measured 774us config. Layer 2 also emits head partials (y @ W_lin) into
// g_fpart (deterministic slots, no atomics); k_sig reduces them.
#define BM 128
#define BN 128
#define BK 32
#define PITCH 40                 // halves per smem row; conflict-free word perm
#define TILEB (128 * PITCH * 2)  // 10240 bytes per tile
#define BUFB  (2 * TILEB)        // A + B per buffer = 20480
#define SMEMB (3 * BUFB)         // 61440 bytes

__global__ __launch_bounds__(128, 2) void k_layer_mma(
    const float* __restrict__ brel,
    const float* __restrict__ Wl,
    float* __restrict__ yout, int layer)
{
    extern __shared__ char sm[];

    const __half* A2    = (layer == 1) ? g_xh : g_hh;
    const __half* Wrel  = g_Wh[(layer == 1) ? 0 : 2];   // [N][K] fp16
    const __half* Wroot = g_Wh[(layer == 1) ? 1 : 3];

    const int t = threadIdx.x;
    const int warp = t >> 5, lane = t & 31;
    const int warpM = warp >> 1, warpN = warp & 1;       // 2x2 of 64x64 tiles
    const int g = lane >> 2, t4 = lane & 3;
    const int rowBase = blockIdx.y * BM;
    const int colBase = blockIdx.x * BN;

    float acc[4][8][4];
#pragma unroll
    for (int mm = 0; mm < 4; mm++)
#pragma unroll
        for (int nn = 0; nn < 8; nn++)
#pragma unroll
            for (int q = 0; q < 4; q++) acc[mm][nn][q] = 0.f;

    // 24 K-iterations: it<12 -> (g_meanh, Wrel); it>=12 -> (A2, Wroot)
    auto stage = [&](int it, int buf) {
        const __half* A = (it < 12) ? g_meanh : A2;
        const __half* W = (it < 12) ? Wrel : Wroot;
        int k0 = (it % 12) * BK;
        char* As = sm + buf * BUFB;
        char* Bs = As + TILEB;
#pragma unroll
        for (int i = 0; i < 4; i++) {
            int c = t + i * 128;          // 512 16B chunks each for A and B
            int r = c >> 2;               // tile row 0..127
            int o = (c & 3) * 8;          // half offset within row
            int boff = r * (PITCH * 2) + (c & 3) * 16;
            int grow = rowBase + r;
            cp16(As + boff, A + (size_t)grow * Dd + k0 + o, grow < Nn);
            cp16(Bs + boff, W + (size_t)(colBase + r) * Dd + k0 + o, true);
        }
    };

    auto compute = [&](int buf) {
        const uint32_t* As32 = (const uint32_t*)(sm + buf * BUFB);
        const uint32_t* Bs32 = (const uint32_t*)(sm + buf * BUFB + TILEB);
#pragma unroll
        for (int ks = 0; ks < 2; ks++) {           // two k16 steps per BK=32
            const int kw = ks * 8 + t4;            // b32 word offset in row
            uint32_t a[4][4], b[8][2];
#pragma unroll
            for (int mm = 0; mm < 4; mm++) {
                int r = warpM * 64 + mm * 16 + g;
                a[mm][0] = As32[r * (PITCH / 2) + kw];
                a[mm][1] = As32[(r + 8) * (PITCH / 2) + kw];
                a[mm][2] = As32[r * (PITCH / 2) + kw + 4];
                a[mm][3] = As32[(r + 8) * (PITCH / 2) + kw + 4];
            }
#pragma unroll
            for (int nn = 0; nn < 8; nn++) {
                int n = warpN * 64 + nn * 8 + g;
                b[nn][0] = Bs32[n * (PITCH / 2) + kw];
                b[nn][1] = Bs32[n * (PITCH / 2) + kw + 4];
            }
#pragma unroll
            for (int mm = 0; mm < 4; mm++)
#pragma unroll
                for (int nn = 0; nn < 8; nn++)
                    mma_f16(acc[mm][nn], a[mm], b[nn]);
        }
    };

    stage(0, 0); CP_COMMIT();
    stage(1, 1); CP_COMMIT();
#pragma unroll 1
    for (int it = 0; it < 24; it++) {
        if (it < 23) { CP_WAIT(1); } else { CP_WAIT(0); }
        __syncthreads();                                 // ONE barrier per iter
        if (it + 2 < 24) { stage(it + 2, (it + 2) % 3); CP_COMMIT(); }
        compute(it % 3);
    }

    // epilogue: bias + relu (+ head partials on layer 2)
    const int slot = blockIdx.x * 2 + warpN;   // 0..5 head-partial slot
#pragma unroll
    for (int mm = 0; mm < 4; mm++) {
        float p00 = 0.f, p01 = 0.f, p10 = 0.f, p11 = 0.f;
#pragma unroll
        for (int nn = 0; nn < 8; nn++) {
            int c = colBase + warpN * 64 + nn * 8 + t4 * 2;
            float b0 = brel[c], b1 = brel[c + 1];
            int r0 = rowBase + warpM * 64 + mm * 16 + g;
            int r1 = r0 + 8;
            float v00 = fmaxf(acc[mm][nn][0] + b0, 0.f);
            float v01 = fmaxf(acc[mm][nn][1] + b1, 0.f);
            float v10 = fmaxf(acc[mm][nn][2] + b0, 0.f);
            float v11 = fmaxf(acc[mm][nn][3] + b1, 0.f);
            if (layer == 1) {
                if (r0 < Nn) {
                    __half2 h = __floats2half2_rn(v00, v01);
                    *(__half2*)(g_hh + (size_t)r0 * Dd + c) = h;
                }
                if (r1 < Nn) {
                    __half2 h = __floats2half2_rn(v10, v11);
                    *(__half2*)(g_hh + (size_t)r1 * Dd + c) = h;
                }
            } else {
                if (r0 < Nn) *(float2*)(yout + (size_t)r0 * Dd + c) = make_float2(v00, v01);
                if (r1 < Nn) *(float2*)(yout + (size_t)r1 * Dd + c) = make_float2(v10, v11);
                float wl0a = __ldg(Wl + c * 2),     wl1a = __ldg(Wl + c * 2 + 1);
                float wl0b = __ldg(Wl + c * 2 + 2), wl1b = __ldg(Wl + c * 2 + 3);
                p00 += v00 * wl0a + v01 * wl0b;
                p01 += v00 * wl1a + v01 * wl1b;
                p10 += v10 * wl0a + v11 * wl0b;
                p11 += v10 * wl1a + v11 * wl1b;
            }
        }
        if (layer == 2) {
            // reduce across the t4 quad (lanes differ in bits 0..1)
#pragma unroll
            for (int m = 1; m <= 2; m <<= 1) {
                p00 += __shfl_xor_sync(0xffffffffu, p00, m);
                p01 += __shfl_xor_sync(0xffffffffu, p01, m);
                p10 += __shfl_xor_sync(0xffffffffu, p10, m);
                p11 += __shfl_xor_sync(0xffffffffu, p11, m);
            }
            if (t4 == 0) {
                int r0 = rowBase + warpM * 64 + mm * 16 + g;
                int r1 = r0 + 8;
                if (r0 < Nn) {
                    g_fpart[(size_t)r0 * 12 + slot * 2 + 0] = p00;
                    g_fpart[(size_t)r0 * 12 + slot * 2 + 1] = p01;
                }
                if (r1 < Nn) {
                    g_fpart[(size_t)r1 * 12 + slot * 2 + 0] = p10;
                    g_fpart[(size_t)r1 * 12 + slot * 2 + 1] = p11;
                }
            }
        }
    }
}

// ---------------- head: sum 6 slots + bias + sigmoid ----------------
__global__ void k_sig(const float* __restrict__ bl, float* __restrict__ out) {
    int r = blockIdx.x * blockDim.x + threadIdx.x;
    if (r >= Nn) return;
    const float* p = g_fpart + (size_t)r * 12;
    float s0 = bl[0], s1 = bl[1];
#pragma unroll
    for (int s = 0; s < 6; s++) { s0 += p[s * 2]; s1 += p[s * 2 + 1]; }
    out[r * 2 + 0] = 1.f / (1.f + expf(-s0));
    out[r * 2 + 1] = 1.f / (1.f + expf(-s1));
}

// ---------------- launch ----------------
extern "C" void kernel_launch(void* const* d_in, const int* in_sizes, int n_in,
                              void* d_out, int out_size)
{
    const float* x   = (const float*)d_in[0];
    const void*  ei  = d_in[1];
    const float* ew  = (const float*)d_in[2];
    const float* br1 = (const float*)d_in[4];
    const float* br2 = (const float*)d_in[7];
    const float* Wl  = (const float*)d_in[9];
    const float* bl  = (const float*)d_in[10];

    float* out = (float*)d_out;                 // [N, 2]
    float* y   = out + (size_t)Nn * OUTC;       // [N, 384]

    (void)cudaFuncSetAttribute(k_layer_mma,
                               cudaFuncAttributeMaxDynamicSharedMemorySize,
                               SMEMB);

    dim3 gg(Dd / BN, (Nn + BM - 1) / BM);       // (3, 782)

    k_init<<<9375, 1024>>>((const int*)ei, x,
                           (const float*)d_in[3], (const float*)d_in[5],
                           (const float*)d_in[6], (const float*)d_in[8]);    // 1
    k_scan1<<<(Nn + 1023) / 1024, 1024>>>();                                  // 2
    k_scan23<<<(Nn + 255) / 256, 256>>>();                                    // 3
    k_fill<<<(Ee + 255) / 256, 256>>>(ei, ew);                                // 4
    k_agg<<<(Nn * 32 + 255) / 256, 256>>>(1);                                 // 5
    k_layer_mma<<<gg, 128, SMEMB>>>(br1, Wl, nullptr, 1);                     // 6
    k_agg<<<(Nn * 32 + 255) / 256, 256>>>(2);                                 // 7
    k_layer_mma<<<gg, 128, SMEMB>>>(br2, Wl, y, 2);                           // 8
    k_sig<<<(Nn + 255) / 256, 256>>>(bl, out);                                // 9
}